// round 1
// baseline (speedup 1.0000x reference)
#include <cuda_runtime.h>

// Reference analysis: sample_times are exact integer knots, so the cubic
// spline evaluation degenerates to yT[sample_times] (fractional t == 0
// exactly; all coefficients finite, so 0*c == 0 bit-exactly in fp32).
// Output == mean over (b, j) of (true[b, 10*j] - pred[b, 10*j])^2.

#define BATCH   1024
#define NFRAMES 8192
#define STRIDE  10
#define NSAMP   820                // ceil(8192/10): t = 0,10,...,8190
#define TOTAL   (BATCH * NSAMP)    // 839680

#define NBLK 512
#define NTHR 256

__device__ float g_partial[NBLK];

__global__ __launch_bounds__(NTHR)
void mse_partial_kernel(const float* __restrict__ tf,
                        const float* __restrict__ pf) {
    float acc = 0.0f;
    const int tid    = blockIdx.x * NTHR + threadIdx.x;
    const int nthr   = NBLK * NTHR;
    for (int i = tid; i < TOTAL; i += nthr) {
        int b = i / NSAMP;               // compiler -> mul-shift
        int j = i - b * NSAMP;
        int idx = b * NFRAMES + j * STRIDE;
        float d = tf[idx] - pf[idx];
        acc = fmaf(d, d, acc);
    }

    __shared__ float sm[NTHR];
    sm[threadIdx.x] = acc;
    __syncthreads();
#pragma unroll
    for (int s = NTHR / 2; s >= 32; s >>= 1) {
        if (threadIdx.x < s) sm[threadIdx.x] += sm[threadIdx.x + s];
        __syncthreads();
    }
    if (threadIdx.x < 32) {
        float v = sm[threadIdx.x];
#pragma unroll
        for (int off = 16; off > 0; off >>= 1)
            v += __shfl_down_sync(0xFFFFFFFFu, v, off);
        if (threadIdx.x == 0) g_partial[blockIdx.x] = v;
    }
}

__global__ void mse_final_kernel(float* __restrict__ out) {
    // Single block, deterministic: shared tree reduce over fixed partials.
    __shared__ double sm[NBLK];
    double v = (double)g_partial[threadIdx.x];
    sm[threadIdx.x] = v;
    __syncthreads();
#pragma unroll
    for (int s = NBLK / 2; s > 0; s >>= 1) {
        if (threadIdx.x < s) sm[threadIdx.x] += sm[threadIdx.x + s];
        __syncthreads();
    }
    if (threadIdx.x == 0)
        out[0] = (float)(sm[0] / (double)TOTAL);
}

extern "C" void kernel_launch(void* const* d_in, const int* in_sizes, int n_in,
                              void* d_out, int out_size) {
    const float* tf = (const float*)d_in[0];   // true_frames  (1024, 8192)
    const float* pf = (const float*)d_in[1];   // predicted_frames
    float* out = (float*)d_out;

    mse_partial_kernel<<<NBLK, NTHR>>>(tf, pf);
    mse_final_kernel<<<1, NBLK>>>(out);
}

// round 2
// speedup vs baseline: 1.1662x; 1.1662x over previous
#include <cuda_runtime.h>

// Reference degenerates to: mean over (b, j) of (true[b,10j] - pred[b,10j])^2
// (sample_times are exact integer knots -> spline eval returns knot values).
//
// Single fused kernel: per-block deterministic fp32 reduce -> fixed-point
// int64 atomic accumulate (associative => deterministic) -> last block
// finalizes and resets the accumulators for the next graph replay.

#define ROWS   1024
#define NFRM   8192
#define STRIDE 10
#define NSAMP  820                 // j = 0..819, sample = 10*j
#define NTHR   256
#define SCALE  1073741824.0        // 2^30

__device__ unsigned long long g_acc = 0ULL;
__device__ unsigned int       g_cnt = 0u;

__global__ __launch_bounds__(NTHR)
void mse_fused_kernel(const float* __restrict__ tf,
                      const float* __restrict__ pf,
                      float* __restrict__ out) {
    const int row = blockIdx.x;
    const float* __restrict__ t = tf + (size_t)row * NFRM;
    const float* __restrict__ p = pf + (size_t)row * NFRM;

    float acc = 0.0f;
#pragma unroll 4
    for (int j = threadIdx.x; j < NSAMP; j += NTHR) {
        float a = t[j * STRIDE];
        float b = p[j * STRIDE];
        float d = a - b;
        acc = fmaf(d, d, acc);
    }

    // Deterministic block reduction: warp shuffle + shared across 8 warps.
    __shared__ float sm[NTHR / 32];
#pragma unroll
    for (int off = 16; off > 0; off >>= 1)
        acc += __shfl_down_sync(0xFFFFFFFFu, acc, off);
    if ((threadIdx.x & 31) == 0) sm[threadIdx.x >> 5] = acc;
    __syncthreads();

    if (threadIdx.x == 0) {
        float v = sm[0];
#pragma unroll
        for (int w = 1; w < NTHR / 32; w++) v += sm[w];

        // Fixed-point conversion: associative integer accumulation across
        // blocks => bit-identical result for any arrival order.
        long long q = llrint((double)v * SCALE);
        atomicAdd(&g_acc, (unsigned long long)q);
        __threadfence();
        unsigned int old = atomicAdd(&g_cnt, 1u);
        if (old == (unsigned int)(gridDim.x - 1)) {
            unsigned long long total = atomicAdd(&g_acc, 0ULL);  // coherent read
            out[0] = (float)(((double)(long long)total / SCALE)
                             / (double)((long long)ROWS * NSAMP));
            // Reset for the next graph replay (serialized by stream order).
            g_cnt = 0u;
            g_acc = 0ULL;
        }
    }
}

extern "C" void kernel_launch(void* const* d_in, const int* in_sizes, int n_in,
                              void* d_out, int out_size) {
    const float* tf = (const float*)d_in[0];   // true_frames  (1024, 8192)
    const float* pf = (const float*)d_in[1];   // predicted_frames
    float* out = (float*)d_out;

    mse_fused_kernel<<<ROWS, NTHR>>>(tf, pf, out);
}

// round 4
// speedup vs baseline: 1.1696x; 1.0029x over previous
#include <cuda_runtime.h>

// Reference degenerates to: mean over (b, j) of (true[b,10j] - pred[b,10j])^2
// (sample_times are exact integer knots -> spline eval returns knot values).
//
// R3: static work schedule for max MLP. 839680 samples = 820 blocks x 256
// threads x 4 samples, fully unrolled -> 8 independent front-batched LDGs
// per thread. Flattened index i -> (row=i/820, j=i%820):
//   gmem idx = row*8192 + j*10 = 10*i - 8*row.
// Deterministic: per-block fp32 reduce (fixed shape) -> fixed-point int64
// atomic accumulate (associative) -> last block finalizes + resets.

#define ROWS   1024
#define NFRM   8192
#define NSAMP  820
#define NBLK   820
#define NTHR   256
#define KPT    4
#define SCALE  1073741824.0        // 2^30

__device__ unsigned long long g_acc = 0ULL;
__device__ unsigned int       g_cnt = 0u;

__global__ __launch_bounds__(NTHR)
void mse_fused_kernel(const float* __restrict__ tf,
                      const float* __restrict__ pf,
                      float* __restrict__ out) {
    const unsigned base = blockIdx.x * (NTHR * KPT) + threadIdx.x;

    // Compute the 4 gather indices (all in range by construction).
    unsigned idx[KPT];
#pragma unroll
    for (int k = 0; k < KPT; k++) {
        unsigned i   = base + k * NTHR;
        unsigned row = i / NSAMP;           // umulhi + shift
        idx[k] = 10u * i - 8u * row;        // == row*8192 + (i%820)*10
    }

    // Front-batched independent loads: 8 outstanding LDGs per thread.
    float a[KPT], b[KPT];
#pragma unroll
    for (int k = 0; k < KPT; k++) a[k] = __ldg(tf + idx[k]);
#pragma unroll
    for (int k = 0; k < KPT; k++) b[k] = __ldg(pf + idx[k]);

    float acc = 0.0f;
#pragma unroll
    for (int k = 0; k < KPT; k++) {
        float d = a[k] - b[k];
        acc = fmaf(d, d, acc);
    }

    // Deterministic block reduction: warp shuffle + shared across 8 warps.
    __shared__ float sm[NTHR / 32];
#pragma unroll
    for (int off = 16; off > 0; off >>= 1)
        acc += __shfl_down_sync(0xFFFFFFFFu, acc, off);
    if ((threadIdx.x & 31) == 0) sm[threadIdx.x >> 5] = acc;
    __syncthreads();

    if (threadIdx.x == 0) {
        float v = sm[0];
#pragma unroll
        for (int w = 1; w < NTHR / 32; w++) v += sm[w];

        // Fixed-point: integer adds are associative => deterministic.
        long long q = llrint((double)v * SCALE);
        atomicAdd(&g_acc, (unsigned long long)q);
        __threadfence();
        unsigned int old = atomicAdd(&g_cnt, 1u);
        if (old == (unsigned int)(gridDim.x - 1)) {
            unsigned long long total = atomicAdd(&g_acc, 0ULL);
            out[0] = (float)(((double)(long long)total / SCALE)
                             / (double)((long long)ROWS * NSAMP));
            g_cnt = 0u;      // reset for next graph replay
            g_acc = 0ULL;
        }
    }
}

extern "C" void kernel_launch(void* const* d_in, const int* in_sizes, int n_in,
                              void* d_out, int out_size) {
    const float* tf = (const float*)d_in[0];   // true_frames  (1024, 8192)
    const float* pf = (const float*)d_in[1];   // predicted_frames
    float* out = (float*)d_out;

    mse_fused_kernel<<<NBLK, NTHR>>>(tf, pf, out);
}